// round 17
// baseline (speedup 1.0000x reference)
#include <cuda_runtime.h>
#include <cuda_fp16.h>

#define N_NODES 100000
#define N_EDGES 1000000
#define NP_GRID 444                        // 148 SMs x 3 CTAs = full residency
#define NP_WARPS (NP_GRID * 8)             // 3552 warps
#define NP_TSTRIDE (NP_GRID * 256u)        // 113664 threads
#define N4 (N_NODES * 4)                   // 400000 float4 slots

__device__ __half g_t[N_NODES * 64];    // [n][o][c] fp16
__device__ __half g_tb[N_NODES * 16];   // [n][o]    fp16
__device__ float  g_r[N_NODES * 16];    // [n][o]    fp32: v@root + bias
__device__ float  g_sum[N_NODES * 16];  // scatter accumulator
__device__ float  g_cnt[N_NODES];       // degree accumulator
__device__ float  g_s1[16];             // batch sum per feature
__device__ float  g_s2[16];             // batch sum-of-squares per feature
__device__ int    g_count;              // barrier arrival count (self-resets)
__device__ int    g_flag;               // barrier sense flag (monotonic)

// Sense-reversing grid barrier. Safe across replays: count returns to 0 at
// each barrier completion; flag only ever increments (equality-test spin).
// Flag read happens before this block's arrival, so the flag cannot advance
// past my+1 while I spin; consecutive barriers are safe.
__device__ __forceinline__ void grid_barrier() {
    __syncthreads();
    if (threadIdx.x == 0) {
        __threadfence();
        int my = atomicAdd(&g_flag, 0);
        int ticket = atomicAdd(&g_count, 1);
        if (ticket == NP_GRID - 1) {
            atomicExch(&g_count, 0);
            atomicAdd(&g_flag, 1);
        } else {
            while (atomicAdd(&g_flag, 0) == my) { }
        }
        __threadfence();
    }
    __syncthreads();
}

// ---------------------------------------------------------------------------
// Single persistent kernel: zero -> node precompute -> [bar] -> edge scatter
// -> [bar] -> finalize + BN-stats -> [bar] -> BN apply.
// ---------------------------------------------------------------------------
__global__ void __launch_bounds__(256, 3) k_fused(
    const float* __restrict__ v,
    const float* __restrict__ efeat,
    const int*   __restrict__ ei,       // [2][E] row0=src, row1=dst
    const float* __restrict__ enet_w,   // [256][4]
    const float* __restrict__ enet_b,   // [256]
    const float* __restrict__ root,     // [16][16] (i,o)
    const float* __restrict__ bias,     // [16]
    const float* __restrict__ gamma,
    const float* __restrict__ beta,
    float* __restrict__ out)
{
    __shared__ __align__(16) float sbuf[2][8][32];   // node-phase v staging
    __shared__ float sm1[8][4][4];
    __shared__ float sm2[8][4][4];

    int t = threadIdx.x;
    int lane = t & 31;
    int warp = t >> 5;
    int cp = lane >> 4;
    int o = lane & 15;
    unsigned gid = blockIdx.x * 256u + t;

    // ===== phase 0: zero accumulators =====
    const float4 z4 = make_float4(0.f, 0.f, 0.f, 0.f);
    for (unsigned i = gid; i < N4; i += NP_TSTRIDE)
        reinterpret_cast<float4*>(g_sum)[i] = z4;
    for (unsigned i = gid; i < N_NODES; i += NP_TSTRIDE) g_cnt[i] = 0.0f;
    if (gid < 16) { g_s1[gid] = 0.0f; g_s2[gid] = 0.0f; }

    // ===== phase 1: node precompute (R16 cp.async pipeline) =====
    {
        float w0[16], w1[16], br[16];
        const float* brbase = (cp == 0) ? enet_b : root;
#pragma unroll
        for (int i = 0; i < 16; i++) {
            int j = i * 16 + o;
            float2 wp = __ldg(reinterpret_cast<const float2*>(enet_w + j * 4 + cp * 2));
            w0[i] = wp.x;
            w1[i] = wp.y;
            br[i] = __ldg(brbase + j);
        }
        float b0 = (cp == 0) ? 0.0f : bias[o];

        int wg = blockIdx.x * 8 + warp;

        auto prefetch = [&](int p, int b) {
            int n0 = wg + p * (2 * NP_WARPS);
            if (n0 >= N_NODES) n0 = 0;
            int n1 = n0 + NP_WARPS;
            if (n1 >= N_NODES) n1 = n0;
            if (lane < 8) {
                const float* src = (lane < 4)
                    ? (v + (unsigned)n0 * 16u + lane * 4)
                    : (v + (unsigned)n1 * 16u + (lane - 4) * 4);
                unsigned dst = (unsigned)__cvta_generic_to_shared(&sbuf[b][warp][lane * 4]);
                asm volatile("cp.async.cg.shared.global [%0], [%1], 16;"
                             :: "r"(dst), "l"(src) : "memory");
            }
            asm volatile("cp.async.commit_group;" ::: "memory");
        };

        prefetch(0, 0);
        int buf = 0;
        int p = 0;
        for (int n0 = wg; n0 < N_NODES; n0 += 2 * NP_WARPS, p++) {
            prefetch(p + 1, buf ^ 1);
            asm volatile("cp.async.wait_group 1;" ::: "memory");
            __syncwarp();

            int n1 = n0 + NP_WARPS;
            bool has1 = (n1 < N_NODES);

            const float4* bufA = reinterpret_cast<const float4*>(&sbuf[buf][warp][0]);
            const float4* bufB = reinterpret_cast<const float4*>(&sbuf[buf][warp][16]);

            float x0 = 0.f, x1 = 0.f, xb = b0;
            float y0 = 0.f, y1 = 0.f, yb = b0;
#pragma unroll
            for (int q = 0; q < 4; q++) {
                float4 xa = bufA[q];
                float4 xv = bufB[q];
                int i = q * 4;
                x0 = fmaf(xa.x, w0[i+0], x0); y0 = fmaf(xv.x, w0[i+0], y0);
                x1 = fmaf(xa.x, w1[i+0], x1); y1 = fmaf(xv.x, w1[i+0], y1);
                xb = fmaf(xa.x, br[i+0], xb); yb = fmaf(xv.x, br[i+0], yb);
                x0 = fmaf(xa.y, w0[i+1], x0); y0 = fmaf(xv.y, w0[i+1], y0);
                x1 = fmaf(xa.y, w1[i+1], x1); y1 = fmaf(xv.y, w1[i+1], y1);
                xb = fmaf(xa.y, br[i+1], xb); yb = fmaf(xv.y, br[i+1], yb);
                x0 = fmaf(xa.z, w0[i+2], x0); y0 = fmaf(xv.z, w0[i+2], y0);
                x1 = fmaf(xa.z, w1[i+2], x1); y1 = fmaf(xv.z, w1[i+2], y1);
                xb = fmaf(xa.z, br[i+2], xb); yb = fmaf(xv.z, br[i+2], yb);
                x0 = fmaf(xa.w, w0[i+3], x0); y0 = fmaf(xv.w, w0[i+3], y0);
                x1 = fmaf(xa.w, w1[i+3], x1); y1 = fmaf(xv.w, w1[i+3], y1);
                xb = fmaf(xa.w, br[i+3], xb); yb = fmaf(xv.w, br[i+3], yb);
            }

            {
                __half2 h = __floats2half2_rn(x0, x1);
                *reinterpret_cast<__half2*>(g_t + (unsigned)n0 * 64u + o * 4u + cp * 2u) = h;
                if (cp == 0) g_tb[(unsigned)n0 * 16u + o] = __float2half_rn(xb);
                else         g_r[(unsigned)n0 * 16u + o] = xb;
            }
            if (has1) {
                __half2 h = __floats2half2_rn(y0, y1);
                *reinterpret_cast<__half2*>(g_t + (unsigned)n1 * 64u + o * 4u + cp * 2u) = h;
                if (cp == 0) g_tb[(unsigned)n1 * 16u + o] = __float2half_rn(yb);
                else         g_r[(unsigned)n1 * 16u + o] = yb;
            }
            buf ^= 1;
        }
        asm volatile("cp.async.wait_group 0;" ::: "memory");
    }

    grid_barrier();   // g_t/g_tb/g_r + zeroed g_sum/g_cnt visible everywhere

    // ===== phase 2: edge messages + RED scatter (R12 body, grid-stride) =====
    {
        unsigned j = gid & 3u;            // NP_TSTRIDE % 4 == 0 -> invariant
        for (unsigned i = gid; i < N_EDGES * 4u; i += NP_TSTRIDE) {
            unsigned eid = i >> 2;

            int src = __ldg(ei + eid);
            int dst = __ldg(ei + N_EDGES + eid);

            float4 ev = __ldg(reinterpret_cast<const float4*>(efeat) + eid);

            const uint4* tp = reinterpret_cast<const uint4*>(g_t + (unsigned)src * 64u + j * 16u);
            uint4 ta = __ldg(tp);
            uint4 tb = __ldg(tp + 1);
            uint2 tbr = __ldg(reinterpret_cast<const uint2*>(g_tb + (unsigned)src * 16u + j * 4u));

#define H2F(u) __half22float2(*reinterpret_cast<__half2*>(&(u)))
            float2 b01 = H2F(tbr.x), b23 = H2F(tbr.y);
            float2 c0 = H2F(ta.x), c1 = H2F(ta.y), c2 = H2F(ta.z), c3 = H2F(ta.w);
            float2 c4 = H2F(tb.x), c5 = H2F(tb.y), c6 = H2F(tb.z), c7 = H2F(tb.w);
#undef H2F
            float m0 = fmaf(ev.x, c0.x, fmaf(ev.y, c0.y, fmaf(ev.z, c1.x, fmaf(ev.w, c1.y, b01.x))));
            float m1 = fmaf(ev.x, c2.x, fmaf(ev.y, c2.y, fmaf(ev.z, c3.x, fmaf(ev.w, c3.y, b01.y))));
            float m2 = fmaf(ev.x, c4.x, fmaf(ev.y, c4.y, fmaf(ev.z, c5.x, fmaf(ev.w, c5.y, b23.x))));
            float m3 = fmaf(ev.x, c6.x, fmaf(ev.y, c6.y, fmaf(ev.z, c7.x, fmaf(ev.w, c7.y, b23.y))));

            float* outp = g_sum + (unsigned)dst * 16u + j * 4u;
            asm volatile("red.global.add.v4.f32 [%0], {%1, %2, %3, %4};"
                         :: "l"(outp), "f"(m0), "f"(m1), "f"(m2), "f"(m3) : "memory");
            if (j == 0) {
                float* cptr = g_cnt + dst;
                asm volatile("red.global.add.f32 [%0], %1;" :: "l"(cptr), "f"(1.0f) : "memory");
            }
        }
    }

    grid_barrier();   // all REDs complete

    // ===== phase 3: finalize + BN stats -> [bar] -> BN apply =====
    {
        float4 vals[4];
        float s1x = 0.f, s1y = 0.f, s1z = 0.f, s1w = 0.f;
        float s2x = 0.f, s2y = 0.f, s2z = 0.f, s2w = 0.f;
#pragma unroll
        for (int k = 0; k < 4; k++) {
            unsigned i = gid + k * NP_TSTRIDE;
            if (i < N4) {
                unsigned n = i >> 2;
                float cnt = __ldcg(g_cnt + n);
                float inv = 1.0f / fmaxf(cnt, 1.0f);
                float4 s = __ldcg(reinterpret_cast<const float4*>(g_sum) + i);
                float4 r = __ldcg(reinterpret_cast<const float4*>(g_r) + i);
                float4 val;
                val.x = fmaf(s.x, inv, r.x);
                val.y = fmaf(s.y, inv, r.y);
                val.z = fmaf(s.z, inv, r.z);
                val.w = fmaf(s.w, inv, r.w);
                vals[k] = val;
                s1x += val.x; s1y += val.y; s1z += val.z; s1w += val.w;
                s2x = fmaf(val.x, val.x, s2x);
                s2y = fmaf(val.y, val.y, s2y);
                s2z = fmaf(val.z, val.z, s2z);
                s2w = fmaf(val.w, val.w, s2w);
            } else {
                vals[k] = make_float4(0.f, 0.f, 0.f, 0.f);
            }
        }

#pragma unroll
        for (int m = 4; m <= 16; m <<= 1) {
            s1x += __shfl_xor_sync(0xffffffffu, s1x, m);
            s1y += __shfl_xor_sync(0xffffffffu, s1y, m);
            s1z += __shfl_xor_sync(0xffffffffu, s1z, m);
            s1w += __shfl_xor_sync(0xffffffffu, s1w, m);
            s2x += __shfl_xor_sync(0xffffffffu, s2x, m);
            s2y += __shfl_xor_sync(0xffffffffu, s2y, m);
            s2z += __shfl_xor_sync(0xffffffffu, s2z, m);
            s2w += __shfl_xor_sync(0xffffffffu, s2w, m);
        }
        if (lane < 4) {
            sm1[warp][lane][0] = s1x; sm1[warp][lane][1] = s1y;
            sm1[warp][lane][2] = s1z; sm1[warp][lane][3] = s1w;
            sm2[warp][lane][0] = s2x; sm2[warp][lane][1] = s2y;
            sm2[warp][lane][2] = s2z; sm2[warp][lane][3] = s2w;
        }
        __syncthreads();
        if (t < 16) {
            float a1 = 0.f, a2 = 0.f;
#pragma unroll
            for (int w = 0; w < 8; w++) {
                a1 += sm1[w][t >> 2][t & 3];
                a2 += sm2[w][t >> 2][t & 3];
            }
            atomicAdd(&g_s1[t], a1);
            atomicAdd(&g_s2[t], a2);
        }

        grid_barrier();   // all stat contributions visible

        int ob = (gid & 3) * 4;
        const float invN = 1.0f / (float)N_NODES;
        float scale[4], shift[4];
#pragma unroll
        for (int k = 0; k < 4; k++) {
            int oo = ob + k;
            float mu = __ldcg(&g_s1[oo]) * invN;
            float var = __ldcg(&g_s2[oo]) * invN - mu * mu;
            float sc = gamma[oo] * rsqrtf(var + 1e-5f);
            scale[k] = sc;
            shift[k] = beta[oo] - sc * mu;
        }
#pragma unroll
        for (int k = 0; k < 4; k++) {
            unsigned i = gid + k * NP_TSTRIDE;
            if (i < N4) {
                float4 val = vals[k];
                float x0 = fmaf(val.x, scale[0], shift[0]);
                float x1 = fmaf(val.y, scale[1], shift[1]);
                float x2 = fmaf(val.z, scale[2], shift[2]);
                float x3 = fmaf(val.w, scale[3], shift[3]);
                float4 res;
                res.x = (x0 >= 0.0f) ? x0 : 0.01f * x0;
                res.y = (x1 >= 0.0f) ? x1 : 0.01f * x1;
                res.z = (x2 >= 0.0f) ? x2 : 0.01f * x2;
                res.w = (x3 >= 0.0f) ? x3 : 0.01f * x3;
                reinterpret_cast<float4*>(out)[i] = res;
            }
        }
    }
}

// ---------------------------------------------------------------------------
extern "C" void kernel_launch(void* const* d_in, const int* in_sizes, int n_in,
                              void* d_out, int out_size) {
    const float* v      = (const float*)d_in[0];
    const float* e      = (const float*)d_in[1];
    const int*   ei     = (const int*)  d_in[2];
    const float* enet_w = (const float*)d_in[3];
    const float* enet_b = (const float*)d_in[4];
    const float* root   = (const float*)d_in[5];
    const float* bias   = (const float*)d_in[6];
    const float* gamma  = (const float*)d_in[7];
    const float* beta   = (const float*)d_in[8];
    float* out = (float*)d_out;

    k_fused<<<NP_GRID, 256>>>(v, e, ei, enet_w, enet_b, root, bias,
                              gamma, beta, out);
}